// round 12
// baseline (speedup 1.0000x reference)
#include <cuda_runtime.h>
#include <cuda_bf16.h>
#include <cuda_fp16.h>
#include <cstdint>

// GCN_26817775797032: 3-layer GCN, N=50000 nodes, E=640000 edges,
// dims 256 -> 128 -> 128 -> 16.
//
// R9: (a) warp-parallel decoupled lookback in the scan (was a 48-hop serial
// poll chain, 9.6us); (b) zero kernel replaced by a graph memset node +
// per-block dtype detection (no global ordering dep); (c) H activations in
// fp16 (halves agg writes and GEMM-L2/gemm16 A-traffic).

#define NN 50000
#define NE 640000
#define HID 128
#define NCLS 16
#define NT4 12500           // NN/4, exact
#define SCAN_BLOCKS 49      // ceil(12500/256)

// ---------------- device scratch (no allocs allowed) ----------------
__device__ __align__(16) int g_deg[NN];
__device__ int   g_rowstart[NN + 1];
__device__ int   g_cursor[NN];
__device__ int   g_csr[NE];
__device__ float g_dis[NN];
__device__ unsigned long long g_scanstate[SCAN_BLOCKS];
__device__ __align__(16) __half g_Gh[(size_t)NN * HID];   // fp16 gather table (layers 1,2)
__device__ __align__(16) float  g_G16[(size_t)NN * NCLS]; // fp32 gather table (layer 3)
__device__ __align__(16) __half g_Hh[(size_t)NN * HID];   // layer activations (fp16)

// ---------------- helpers ----------------
__device__ __forceinline__ float4 f4add(float4 a, float4 b) {
    a.x += b.x; a.y += b.y; a.z += b.z; a.w += b.w; return a;
}

__device__ __forceinline__ uint32_t f2tf32(float f) {
    uint32_t u;
    asm("cvt.rna.tf32.f32 %0, %1;" : "=r"(u) : "f"(f));
    return u;
}

__device__ __forceinline__ void mma_tf32(float* d, const uint32_t* a, const uint32_t* b) {
    asm volatile(
        "mma.sync.aligned.m16n8k8.row.col.f32.tf32.tf32.f32 "
        "{%0,%1,%2,%3}, {%4,%5,%6,%7}, {%8,%9}, {%0,%1,%2,%3};"
        : "+f"(d[0]), "+f"(d[1]), "+f"(d[2]), "+f"(d[3])
        : "r"(a[0]), "r"(a[1]), "r"(a[2]), "r"(a[3]), "r"(b[0]), "r"(b[1]));
}

__device__ __forceinline__ float4 h8_to_f4_sum(uint2 v, float w, float4 acc) {
    float2 q0 = __half22float2(*(__half2*)&v.x);
    float2 q1 = __half22float2(*(__half2*)&v.y);
    acc.x += w * q0.x; acc.y += w * q0.y;
    acc.z += w * q1.x; acc.w += w * q1.y;
    return acc;
}

// Per-block dtype detection: warp 0 range-checks the first 32 int64 words.
// int32 data packs two ids per word -> high halves nonzero -> fails check.
__device__ __forceinline__ int detect_is64_block(const void* __restrict__ ei,
                                                 int* s_flag) {
    if (threadIdx.x < 32) {
        const long long* p = (const long long*)ei;
        long long v = p[threadIdx.x];
        unsigned bad = __ballot_sync(0xFFFFFFFFu, v < 0 || v >= NN);
        if (threadIdx.x == 0) *s_flag = (bad == 0u);
    }
    __syncthreads();
    return *s_flag;
}

__device__ __forceinline__ int load_idx(const void* __restrict__ ei, int i, int is64) {
    if (is64) return (int)((const long long*)ei)[i];
    return ((const int*)ei)[i];
}

// ---------------- preprocessing ----------------
__global__ void deg_kernel(const void* __restrict__ ei) {
    __shared__ int s_is64;
    int is64 = detect_is64_block(ei, &s_is64);
    int e = blockIdx.x * blockDim.x + threadIdx.x;
    if (e < SCAN_BLOCKS) g_scanstate[e] = 0ULL;
    if (e < NE) {
        int d = load_idx(ei, NE + e, is64);
        if (d >= 0 && d < NN) atomicAdd(&g_deg[d], 1);
    }
}

// ---- fused single-pass scan, warp-parallel decoupled lookback ----
__global__ __launch_bounds__(256) void scan_fused_kernel() {
    int tid  = threadIdx.x;
    int lane = tid & 31;
    int warp = tid >> 5;
    int bid  = blockIdx.x;
    int t    = bid * 256 + tid;

    int4 v = make_int4(0, 0, 0, 0);
    if (t < NT4) v = ((const int4*)g_deg)[t];
    int s = v.x + v.y + v.z + v.w;

    // warp inclusive scan
    int inc = s;
#pragma unroll
    for (int o = 1; o < 32; o <<= 1) {
        int u = __shfl_up_sync(0xFFFFFFFFu, inc, o);
        if (lane >= o) inc += u;
    }
    __shared__ int wsum[8], woff[8];
    __shared__ int blk_excl;
    if (lane == 31) wsum[warp] = inc;
    __syncthreads();
    if (tid < 8) {
        int w  = wsum[tid];
        int wi = w;
#pragma unroll
        for (int o = 1; o < 8; o <<= 1) {
            int u = __shfl_up_sync(0xFFu, wi, o);
            if (tid >= o) wi += u;
        }
        woff[tid] = wi - w;   // exclusive warp offset
    }
    __syncthreads();

    if (warp == 0) {
        long long bt = (long long)(woff[7] + wsum[7]);   // block total
        if (bid == 0) {
            if (lane == 0) {
                atomicExch(&g_scanstate[0], (((unsigned long long)bt) << 2) | 2ULL);
                blk_excl = 0;
                g_rowstart[NN] = (SCAN_BLOCKS == 1) ? (int)bt : g_rowstart[NN];
            }
        } else {
            if (lane == 0)
                atomicExch(&g_scanstate[bid], (((unsigned long long)bt) << 2) | 1ULL);
            __syncwarp();

            long long excl = 0;   // meaningful on lane 0 only
            int p = bid - 1;
            while (true) {
                int idx = p - lane;
                unsigned long long st = (idx >= 0)
                    ? atomicAdd(&g_scanstate[idx], 0ULL) : 2ULL;  // idx<0: prefix 0
                unsigned f  = (unsigned)(st & 3ULL);
                unsigned b2 = __ballot_sync(0xFFFFFFFFu, f == 2u);
                unsigned b0 = __ballot_sync(0xFFFFFFFFu, f == 0u);
                if (b2 != 0u) {
                    int fp = __ffs(b2) - 1;   // nearest lane holding a prefix
                    if ((b0 & ((1u << fp) - 1u)) == 0u) {
                        long long val = (lane <= fp) ? (long long)(st >> 2) : 0LL;
#pragma unroll
                        for (int o = 16; o > 0; o >>= 1)
                            val += __shfl_down_sync(0xFFFFFFFFu, val, o);
                        if (lane == 0) excl += val;
                        break;
                    }
                } else if (b0 == 0u) {
                    // all 32 are aggregates: consume the window, move left
                    long long val = (long long)(st >> 2);
#pragma unroll
                    for (int o = 16; o > 0; o >>= 1)
                        val += __shfl_down_sync(0xFFFFFFFFu, val, o);
                    if (lane == 0) excl += val;
                    p -= 32;
                }
            }
            if (lane == 0) {
                atomicExch(&g_scanstate[bid],
                           (((unsigned long long)(excl + bt)) << 2) | 2ULL);
                blk_excl = (int)excl;
                if (bid == SCAN_BLOCKS - 1) g_rowstart[NN] = (int)(excl + bt);
            }
        }
    }
    __syncthreads();

    if (t < NT4) {
        int off = (inc - s) + woff[warp] + blk_excl;
        int base = t * 4;
        g_rowstart[base + 0] = off; g_cursor[base + 0] = off;
        g_dis[base + 0] = rsqrtf(1.0f + (float)v.x); off += v.x;
        g_rowstart[base + 1] = off; g_cursor[base + 1] = off;
        g_dis[base + 1] = rsqrtf(1.0f + (float)v.y); off += v.y;
        g_rowstart[base + 2] = off; g_cursor[base + 2] = off;
        g_dis[base + 2] = rsqrtf(1.0f + (float)v.z); off += v.z;
        g_rowstart[base + 3] = off; g_cursor[base + 3] = off;
        g_dis[base + 3] = rsqrtf(1.0f + (float)v.w);
    }
}

__global__ void fill_kernel(const void* __restrict__ ei) {
    __shared__ int s_is64;
    int is64 = detect_is64_block(ei, &s_is64);
    int e = blockIdx.x * blockDim.x + threadIdx.x;
    if (e < NE) {
        int s = load_idx(ei, e, is64);
        int d = load_idx(ei, NE + e, is64);
        if (s >= 0 && s < NN && d >= 0 && d < NN) {
            int pos = atomicAdd(&g_cursor[d], 1);
            if (pos >= 0 && pos < NE) g_csr[pos] = s;
        }
    }
}

// ---------------- GEMM (tf32 tensor cores): [NN x K] @ [K x 128] -> g_Gh (fp16) ----
// srcH=1: A = g_Hh (fp16). scale_dis: multiply rows by dis[row] in epilogue.
__global__ __launch_bounds__(256) void gemm128_tc_kernel(
    const float* __restrict__ Aext, const float* __restrict__ W, int K, int srcH,
    int scale_dis)
{
    __shared__ uint32_t As[16][136];
    __shared__ uint32_t Bs[16][136];

    int tid  = threadIdx.x;
    int warp = tid >> 5;
    int lane = tid & 31;
    int g    = lane >> 2;
    int t4   = lane & 3;
    int m0   = blockIdx.x * 128;
    int wm   = (warp >> 2) * 64;
    int wn   = (warp & 3) * 32;

    float acc[4][4][4];
#pragma unroll
    for (int mi = 0; mi < 4; mi++)
#pragma unroll
        for (int ni = 0; ni < 4; ni++)
#pragma unroll
            for (int r = 0; r < 4; r++) acc[mi][ni][r] = 0.0f;

    for (int k0 = 0; k0 < K; k0 += 16) {
#pragma unroll
        for (int i = 0; i < 2; i++) {
            int l   = tid * 2 + i;
            int row = l >> 2;
            int kc  = (l & 3) << 2;
            int gr  = m0 + row;
            float4 v = make_float4(0.f, 0.f, 0.f, 0.f);
            if (gr < NN) {
                if (srcH) {
                    uint2 u = *(const uint2*)(g_Hh + (size_t)gr * 128 + k0 + kc);
                    float2 a0 = __half22float2(*(__half2*)&u.x);
                    float2 a1 = __half22float2(*(__half2*)&u.y);
                    v = make_float4(a0.x, a0.y, a1.x, a1.y);
                } else {
                    v = *(const float4*)(Aext + (size_t)gr * K + k0 + kc);
                }
            }
            As[kc + 0][row] = f2tf32(v.x);
            As[kc + 1][row] = f2tf32(v.y);
            As[kc + 2][row] = f2tf32(v.z);
            As[kc + 3][row] = f2tf32(v.w);
        }
#pragma unroll
        for (int i = 0; i < 2; i++) {
            int l  = tid * 2 + i;
            int kr = l >> 5;
            int nc = (l & 31) << 2;
            float4 v = *(const float4*)(W + (size_t)(k0 + kr) * 128 + nc);
            Bs[kr][nc + 0] = f2tf32(v.x);
            Bs[kr][nc + 1] = f2tf32(v.y);
            Bs[kr][nc + 2] = f2tf32(v.z);
            Bs[kr][nc + 3] = f2tf32(v.w);
        }
        __syncthreads();

#pragma unroll
        for (int kk = 0; kk < 16; kk += 8) {
            uint32_t af[4][4];
#pragma unroll
            for (int mi = 0; mi < 4; mi++) {
                int m = wm + mi * 16 + g;
                af[mi][0] = As[kk + t4][m];
                af[mi][1] = As[kk + t4][m + 8];
                af[mi][2] = As[kk + t4 + 4][m];
                af[mi][3] = As[kk + t4 + 4][m + 8];
            }
            uint32_t bf[4][2];
#pragma unroll
            for (int ni = 0; ni < 4; ni++) {
                int n = wn + ni * 8 + g;
                bf[ni][0] = Bs[kk + t4][n];
                bf[ni][1] = Bs[kk + t4 + 4][n];
            }
#pragma unroll
            for (int mi = 0; mi < 4; mi++)
#pragma unroll
                for (int ni = 0; ni < 4; ni++)
                    mma_tf32(acc[mi][ni], af[mi], bf[ni]);
        }
        __syncthreads();
    }

#pragma unroll
    for (int mi = 0; mi < 4; mi++) {
        int r0 = m0 + wm + mi * 16 + g;
        int r1 = r0 + 8;
        float d0 = 1.0f, d1 = 1.0f;
        if (scale_dis) {
            d0 = (r0 < NN) ? g_dis[r0] : 0.0f;
            d1 = (r1 < NN) ? g_dis[r1] : 0.0f;
        }
#pragma unroll
        for (int ni = 0; ni < 4; ni++) {
            int c = wn + ni * 8 + 2 * t4;
            if (r0 < NN) {
                __half2 h = __floats2half2_rn(acc[mi][ni][0] * d0, acc[mi][ni][1] * d0);
                *(__half2*)(g_Gh + (size_t)r0 * 128 + c) = h;
            }
            if (r1 < NN) {
                __half2 h = __floats2half2_rn(acc[mi][ni][2] * d1, acc[mi][ni][3] * d1);
                *(__half2*)(g_Gh + (size_t)r1 * 128 + c) = h;
            }
        }
    }
}

// ---------------- GEMM: [NN x 128(fp16)] @ [128 x 16] * dis[row] -> g_G16 (fp32) ------
__global__ __launch_bounds__(256) void gemm16_kernel(const float* __restrict__ W3)
{
    __shared__ float As[16][520];
    __shared__ float Bs[16][16];

    int tid = threadIdx.x;
    int m0  = blockIdx.x * 512;
    int tx  = tid & 1;
    int ty  = tid >> 1;

    float acc[4][8];
#pragma unroll
    for (int r = 0; r < 4; r++)
#pragma unroll
        for (int c = 0; c < 8; c++) acc[r][c] = 0.0f;

    for (int k0 = 0; k0 < 128; k0 += 16) {
#pragma unroll
        for (int i = 0; i < 8; i++) {
            int l   = i * 256 + tid;
            int row = l >> 2;
            int kc  = (l & 3) << 2;
            int gr  = m0 + row;
            float4 v = make_float4(0.f, 0.f, 0.f, 0.f);
            if (gr < NN) {
                uint2 u = *(const uint2*)(g_Hh + (size_t)gr * 128 + k0 + kc);
                float2 a0 = __half22float2(*(__half2*)&u.x);
                float2 a1 = __half22float2(*(__half2*)&u.y);
                v = make_float4(a0.x, a0.y, a1.x, a1.y);
            }
            As[kc + 0][row] = v.x;
            As[kc + 1][row] = v.y;
            As[kc + 2][row] = v.z;
            As[kc + 3][row] = v.w;
        }
        if (tid < 64) {
            int kr = tid >> 2;
            int nc = (tid & 3) << 2;
            *(float4*)&Bs[kr][nc] = *(const float4*)(W3 + (size_t)(k0 + kr) * 16 + nc);
        }
        __syncthreads();

#pragma unroll
        for (int k = 0; k < 16; k++) {
            float4 av = *(const float4*)&As[k][ty * 4];
            float a[4] = {av.x, av.y, av.z, av.w};
            float4 b0 = *(const float4*)&Bs[k][tx * 8];
            float4 b1 = *(const float4*)&Bs[k][tx * 8 + 4];
            float bb[8] = {b0.x,b0.y,b0.z,b0.w,b1.x,b1.y,b1.z,b1.w};
#pragma unroll
            for (int r = 0; r < 4; r++)
#pragma unroll
                for (int c = 0; c < 8; c++)
                    acc[r][c] += a[r] * bb[c];
        }
        __syncthreads();
    }

#pragma unroll
    for (int r = 0; r < 4; r++) {
        int gr = m0 + ty * 4 + r;
        if (gr < NN) {
            float d = g_dis[gr];
            float4 v0 = make_float4(acc[r][0]*d, acc[r][1]*d, acc[r][2]*d, acc[r][3]*d);
            float4 v1 = make_float4(acc[r][4]*d, acc[r][5]*d, acc[r][6]*d, acc[r][7]*d);
            *(float4*)(g_G16 + (size_t)gr * 16 + tx * 8)     = v0;
            *(float4*)(g_G16 + (size_t)gr * 16 + tx * 8 + 4) = v1;
        }
    }
}

// ---------------- Aggregation (128-wide, fp16 gather, fp16 H output) ----------------
// scale_src=1 (layer 1): G unscaled -> H = relu(dis_i*(sum dis_s*G[s] + dis_i*G[i]) + b)
// scale_src=0 (layer 2): G pre-scaled -> H = relu(dis_i*(sum G[s] + G[i]) + b)
__global__ __launch_bounds__(256) void agg128_kernel(const float* __restrict__ bias,
                                                     int scale_src)
{
    int gt   = blockIdx.x * blockDim.x + threadIdx.x;
    int node = gt >> 5;
    int lane = gt & 31;
    if (node >= NN) return;

    const uint2* __restrict__ Gv = (const uint2*)g_Gh;   // row = 32 uint2
    float d = g_dis[node];

    float4 acc = make_float4(0.f, 0.f, 0.f, 0.f);
    acc = h8_to_f4_sum(Gv[node * 32 + lane], scale_src ? d : 1.0f, acc);

    int j  = g_rowstart[node];
    int s1 = g_rowstart[node + 1];
    for (; j + 4 <= s1; j += 4) {
        int sa = g_csr[j],     sb = g_csr[j + 1];
        int sc = g_csr[j + 2], sd = g_csr[j + 3];
        uint2 va = Gv[sa * 32 + lane];
        uint2 vb = Gv[sb * 32 + lane];
        uint2 vc = Gv[sc * 32 + lane];
        uint2 vd = Gv[sd * 32 + lane];
        float wa = 1.0f, wb = 1.0f, wc = 1.0f, wd = 1.0f;
        if (scale_src) { wa = g_dis[sa]; wb = g_dis[sb]; wc = g_dis[sc]; wd = g_dis[sd]; }
        acc = h8_to_f4_sum(va, wa, acc);
        acc = h8_to_f4_sum(vb, wb, acc);
        acc = h8_to_f4_sum(vc, wc, acc);
        acc = h8_to_f4_sum(vd, wd, acc);
    }
    for (; j < s1; j++) {
        int s = g_csr[j];
        acc = h8_to_f4_sum(Gv[s * 32 + lane], scale_src ? g_dis[s] : 1.0f, acc);
    }

    float4 b = ((const float4*)bias)[lane];
    uint2 o;
    *(__half2*)&o.x = __floats2half2_rn(fmaxf(acc.x * d + b.x, 0.0f),
                                        fmaxf(acc.y * d + b.y, 0.0f));
    *(__half2*)&o.y = __floats2half2_rn(fmaxf(acc.z * d + b.z, 0.0f),
                                        fmaxf(acc.w * d + b.w, 0.0f));
    ((uint2*)g_Hh)[(size_t)node * 32 + lane] = o;
}

// ---------------- Aggregation (16-wide, final, fp32) ----------------
__global__ __launch_bounds__(256) void agg16_kernel(const float* __restrict__ bias,
                                                    float* __restrict__ out)
{
    int gt   = blockIdx.x * blockDim.x + threadIdx.x;
    int node = gt >> 2;
    int q    = gt & 3;
    if (node >= NN) return;

    const float4* __restrict__ Gv = (const float4*)g_G16;
    float4 acc = Gv[node * 4 + q];

    int j  = g_rowstart[node];
    int s1 = g_rowstart[node + 1];
    for (; j + 2 <= s1; j += 2) {
        int sa = g_csr[j], sb = g_csr[j + 1];
        float4 va = Gv[sa * 4 + q];
        float4 vb = Gv[sb * 4 + q];
        acc = f4add(acc, f4add(va, vb));
    }
    for (; j < s1; j++) acc = f4add(acc, Gv[g_csr[j] * 4 + q]);

    float d = g_dis[node];
    float4 b = ((const float4*)bias)[q];
    float4 r;
    r.x = acc.x * d + b.x;
    r.y = acc.y * d + b.y;
    r.z = acc.z * d + b.z;
    r.w = acc.w * d + b.w;
    ((float4*)out)[(size_t)node * 4 + q] = r;
}

// ---------------- launch ----------------
extern "C" void kernel_launch(void* const* d_in, const int* in_sizes, int n_in,
                              void* d_out, int out_size)
{
    const float* x  = (const float*)d_in[0];
    const void*  ei = d_in[1];                 // int32 or int64, detected per block
    const float* W1 = (const float*)d_in[2];
    const float* b1 = (const float*)d_in[3];
    const float* W2 = (const float*)d_in[4];
    const float* b2 = (const float*)d_in[5];
    const float* W3 = (const float*)d_in[6];
    const float* b3 = (const float*)d_in[7];
    float* out = (float*)d_out;

    // one-time host-side setup (first call = correctness run, outside capture)
    static cudaStream_t s2 = nullptr;
    static cudaEvent_t  evFork = nullptr, evGemm = nullptr;
    static void* p_deg = nullptr;
    if (!s2) {
        cudaStreamCreateWithFlags(&s2, cudaStreamNonBlocking);
        cudaEventCreateWithFlags(&evFork, cudaEventDisableTiming);
        cudaEventCreateWithFlags(&evGemm, cudaEventDisableTiming);
        cudaGetSymbolAddress(&p_deg, g_deg);
    }

    const int gemm_blocks   = (NN + 127) / 128;        // 391
    const int agg128_blocks = (NN * 32 + 255) / 256;   // 6250
    const int agg16_blocks  = (NN * 4 + 255) / 256;    // 782
    const int gemm16_blocks = (NN + 511) / 512;        // 98

    // Fork: GEMM-L1 (independent of preprocessing; dis deferred to agg)
    cudaEventRecord(evFork, 0);
    cudaStreamWaitEvent(s2, evFork, 0);
    gemm128_tc_kernel<<<gemm_blocks, 256, 0, s2>>>(x, W1, 256, 0, /*scale_dis=*/0);
    cudaEventRecord(evGemm, s2);

    // Main branch: preprocessing (memset node -> deg -> scan -> fill)
    cudaMemsetAsync(p_deg, 0, NN * sizeof(int), 0);
    deg_kernel<<<(NE + 255) / 256, 256>>>(ei);
    scan_fused_kernel<<<SCAN_BLOCKS, 256>>>();
    fill_kernel<<<(NE + 255) / 256, 256>>>(ei);

    // Join, then layer 1 aggregation (applies dis on both sides)
    cudaStreamWaitEvent(0, evGemm, 0);
    agg128_kernel<<<agg128_blocks, 256>>>(b1, /*scale_src=*/1);

    // Layer 2 (A = H fp16; dis in GEMM epilogue)
    gemm128_tc_kernel<<<gemm_blocks, 256>>>(nullptr, W2, 128, 1, /*scale_dis=*/1);
    agg128_kernel<<<agg128_blocks, 256>>>(b2, /*scale_src=*/0);

    // Layer 3: 128 -> 16, no relu (A = H fp16, fp32 math)
    gemm16_kernel<<<gemm16_blocks, 256>>>(W3);
    agg16_kernel<<<agg16_blocks, 256>>>(b3, out);
}

// round 13
// speedup vs baseline: 1.2202x; 1.2202x over previous
#include <cuda_runtime.h>
#include <cuda_bf16.h>
#include <cuda_fp16.h>
#include <cstdint>

// GCN_26817775797032: 3-layer GCN, N=50000 nodes, E=640000 edges,
// dims 256 -> 128 -> 128 -> 16.
//
// R13: (a) 128-wide GEMMs use fp16 mma.sync m16n8k16 (fp32 acc) instead of
// tf32 m16n8k8 -- same 10-bit mantissa, half the MMA instructions and half
// the smem traffic; BK=32. (b) deg/fill process 4 edges per thread (MLP).

#define NN 50000
#define NE 640000
#define HID 128
#define NCLS 16
#define NT4 12500           // NN/4, exact
#define SCAN_BLOCKS 49      // ceil(12500/256)

// ---------------- device scratch (no allocs allowed) ----------------
__device__ __align__(16) int g_deg[NN];
__device__ int   g_rowstart[NN + 1];
__device__ int   g_cursor[NN];
__device__ int   g_csr[NE];
__device__ float g_dis[NN];
__device__ unsigned long long g_scanstate[SCAN_BLOCKS];
__device__ __align__(16) __half g_Gh[(size_t)NN * HID];   // fp16 gather table (layers 1,2)
__device__ __align__(16) float  g_G16[(size_t)NN * NCLS]; // fp32 gather table (layer 3)
__device__ __align__(16) __half g_Hh[(size_t)NN * HID];   // layer activations (fp16)

// ---------------- helpers ----------------
__device__ __forceinline__ float4 f4add(float4 a, float4 b) {
    a.x += b.x; a.y += b.y; a.z += b.z; a.w += b.w; return a;
}

__device__ __forceinline__ uint32_t pack_h2(float x, float y) {
    __half2 h = __floats2half2_rn(x, y);
    return *(uint32_t*)&h;
}

__device__ __forceinline__ void mma_f16(float* d, const uint32_t* a, const uint32_t* b) {
    asm volatile(
        "mma.sync.aligned.m16n8k16.row.col.f32.f16.f16.f32 "
        "{%0,%1,%2,%3}, {%4,%5,%6,%7}, {%8,%9}, {%0,%1,%2,%3};"
        : "+f"(d[0]), "+f"(d[1]), "+f"(d[2]), "+f"(d[3])
        : "r"(a[0]), "r"(a[1]), "r"(a[2]), "r"(a[3]), "r"(b[0]), "r"(b[1]));
}

__device__ __forceinline__ float4 h8_to_f4_sum(uint2 v, float w, float4 acc) {
    float2 q0 = __half22float2(*(__half2*)&v.x);
    float2 q1 = __half22float2(*(__half2*)&v.y);
    acc.x += w * q0.x; acc.y += w * q0.y;
    acc.z += w * q1.x; acc.w += w * q1.y;
    return acc;
}

// Per-block dtype detection: warp 0 range-checks the first 32 int64 words.
// int32 data packs two ids per word -> high halves nonzero -> fails check.
__device__ __forceinline__ int detect_is64_block(const void* __restrict__ ei,
                                                 int* s_flag) {
    if (threadIdx.x < 32) {
        const long long* p = (const long long*)ei;
        long long v = p[threadIdx.x];
        unsigned bad = __ballot_sync(0xFFFFFFFFu, v < 0 || v >= NN);
        if (threadIdx.x == 0) *s_flag = (bad == 0u);
    }
    __syncthreads();
    return *s_flag;
}

__device__ __forceinline__ int load_idx(const void* __restrict__ ei, int i, int is64) {
    if (is64) return (int)((const long long*)ei)[i];
    return ((const int*)ei)[i];
}

// ---------------- preprocessing (4 edges per thread) ----------------
__global__ void deg_kernel(const void* __restrict__ ei) {
    __shared__ int s_is64;
    int is64 = detect_is64_block(ei, &s_is64);
    int t = blockIdx.x * blockDim.x + threadIdx.x;
    if (t < SCAN_BLOCKS) g_scanstate[t] = 0ULL;
    int e0 = t * 4;
    if (e0 + 3 < NE) {
        int d0, d1, d2, d3;
        if (is64) {
            d0 = load_idx(ei, NE + e0 + 0, 1);
            d1 = load_idx(ei, NE + e0 + 1, 1);
            d2 = load_idx(ei, NE + e0 + 2, 1);
            d3 = load_idx(ei, NE + e0 + 3, 1);
        } else {
            int4 d4 = *(const int4*)((const int*)ei + NE + e0);
            d0 = d4.x; d1 = d4.y; d2 = d4.z; d3 = d4.w;
        }
        if (d0 >= 0 && d0 < NN) atomicAdd(&g_deg[d0], 1);
        if (d1 >= 0 && d1 < NN) atomicAdd(&g_deg[d1], 1);
        if (d2 >= 0 && d2 < NN) atomicAdd(&g_deg[d2], 1);
        if (d3 >= 0 && d3 < NN) atomicAdd(&g_deg[d3], 1);
    }
}

// ---- fused single-pass scan, warp-parallel decoupled lookback ----
__global__ __launch_bounds__(256) void scan_fused_kernel() {
    int tid  = threadIdx.x;
    int lane = tid & 31;
    int warp = tid >> 5;
    int bid  = blockIdx.x;
    int t    = bid * 256 + tid;

    int4 v = make_int4(0, 0, 0, 0);
    if (t < NT4) v = ((const int4*)g_deg)[t];
    int s = v.x + v.y + v.z + v.w;

    int inc = s;
#pragma unroll
    for (int o = 1; o < 32; o <<= 1) {
        int u = __shfl_up_sync(0xFFFFFFFFu, inc, o);
        if (lane >= o) inc += u;
    }
    __shared__ int wsum[8], woff[8];
    __shared__ int blk_excl;
    if (lane == 31) wsum[warp] = inc;
    __syncthreads();
    if (tid < 8) {
        int w  = wsum[tid];
        int wi = w;
#pragma unroll
        for (int o = 1; o < 8; o <<= 1) {
            int u = __shfl_up_sync(0xFFu, wi, o);
            if (tid >= o) wi += u;
        }
        woff[tid] = wi - w;
    }
    __syncthreads();

    if (warp == 0) {
        long long bt = (long long)(woff[7] + wsum[7]);
        if (bid == 0) {
            if (lane == 0) {
                atomicExch(&g_scanstate[0], (((unsigned long long)bt) << 2) | 2ULL);
                blk_excl = 0;
            }
        } else {
            if (lane == 0)
                atomicExch(&g_scanstate[bid], (((unsigned long long)bt) << 2) | 1ULL);
            __syncwarp();

            long long excl = 0;
            int p = bid - 1;
            while (true) {
                int idx = p - lane;
                unsigned long long st = (idx >= 0)
                    ? atomicAdd(&g_scanstate[idx], 0ULL) : 2ULL;
                unsigned f  = (unsigned)(st & 3ULL);
                unsigned b2 = __ballot_sync(0xFFFFFFFFu, f == 2u);
                unsigned b0 = __ballot_sync(0xFFFFFFFFu, f == 0u);
                if (b2 != 0u) {
                    int fp = __ffs(b2) - 1;
                    if ((b0 & ((1u << fp) - 1u)) == 0u) {
                        long long val = (lane <= fp) ? (long long)(st >> 2) : 0LL;
#pragma unroll
                        for (int o = 16; o > 0; o >>= 1)
                            val += __shfl_down_sync(0xFFFFFFFFu, val, o);
                        if (lane == 0) excl += val;
                        break;
                    }
                } else if (b0 == 0u) {
                    long long val = (long long)(st >> 2);
#pragma unroll
                    for (int o = 16; o > 0; o >>= 1)
                        val += __shfl_down_sync(0xFFFFFFFFu, val, o);
                    if (lane == 0) excl += val;
                    p -= 32;
                }
            }
            if (lane == 0) {
                atomicExch(&g_scanstate[bid],
                           (((unsigned long long)(excl + bt)) << 2) | 2ULL);
                blk_excl = (int)excl;
                if (bid == SCAN_BLOCKS - 1) g_rowstart[NN] = (int)(excl + bt);
            }
        }
    }
    __syncthreads();

    if (t < NT4) {
        int off = (inc - s) + woff[warp] + blk_excl;
        int base = t * 4;
        g_rowstart[base + 0] = off; g_cursor[base + 0] = off;
        g_dis[base + 0] = rsqrtf(1.0f + (float)v.x); off += v.x;
        g_rowstart[base + 1] = off; g_cursor[base + 1] = off;
        g_dis[base + 1] = rsqrtf(1.0f + (float)v.y); off += v.y;
        g_rowstart[base + 2] = off; g_cursor[base + 2] = off;
        g_dis[base + 2] = rsqrtf(1.0f + (float)v.z); off += v.z;
        g_rowstart[base + 3] = off; g_cursor[base + 3] = off;
        g_dis[base + 3] = rsqrtf(1.0f + (float)v.w);
    }
}

__global__ void fill_kernel(const void* __restrict__ ei) {
    __shared__ int s_is64;
    int is64 = detect_is64_block(ei, &s_is64);
    int e0 = (blockIdx.x * blockDim.x + threadIdx.x) * 4;
    if (e0 + 3 < NE) {
        int s0, s1, s2, s3, d0, d1, d2, d3;
        if (is64) {
            s0 = load_idx(ei, e0 + 0, 1); s1 = load_idx(ei, e0 + 1, 1);
            s2 = load_idx(ei, e0 + 2, 1); s3 = load_idx(ei, e0 + 3, 1);
            d0 = load_idx(ei, NE + e0 + 0, 1); d1 = load_idx(ei, NE + e0 + 1, 1);
            d2 = load_idx(ei, NE + e0 + 2, 1); d3 = load_idx(ei, NE + e0 + 3, 1);
        } else {
            int4 s4 = *(const int4*)((const int*)ei + e0);
            int4 d4 = *(const int4*)((const int*)ei + NE + e0);
            s0 = s4.x; s1 = s4.y; s2 = s4.z; s3 = s4.w;
            d0 = d4.x; d1 = d4.y; d2 = d4.z; d3 = d4.w;
        }
        if (s0 >= 0 && s0 < NN && d0 >= 0 && d0 < NN) {
            int p = atomicAdd(&g_cursor[d0], 1);
            if (p >= 0 && p < NE) g_csr[p] = s0;
        }
        if (s1 >= 0 && s1 < NN && d1 >= 0 && d1 < NN) {
            int p = atomicAdd(&g_cursor[d1], 1);
            if (p >= 0 && p < NE) g_csr[p] = s1;
        }
        if (s2 >= 0 && s2 < NN && d2 >= 0 && d2 < NN) {
            int p = atomicAdd(&g_cursor[d2], 1);
            if (p >= 0 && p < NE) g_csr[p] = s2;
        }
        if (s3 >= 0 && s3 < NN && d3 >= 0 && d3 < NN) {
            int p = atomicAdd(&g_cursor[d3], 1);
            if (p >= 0 && p < NE) g_csr[p] = s3;
        }
    }
}

// ---------------- GEMM (fp16 tensor cores): [NN x K] @ [K x 128] -> g_Gh (fp16) ----
// BM=128, BN=128, BK=32, 256 threads = 8 warps (2x4); warp tile 64x32.
// mma.sync m16n8k16 fp16, fp32 accumulate. smem words = half2 packing (k, k+1).
// srcH=1: A = g_Hh (fp16). scale_dis: multiply rows by dis[row] in epilogue.
__global__ __launch_bounds__(256) void gemm128_tc_kernel(
    const float* __restrict__ Aext, const float* __restrict__ W, int K, int srcH,
    int scale_dis)
{
    __shared__ uint32_t As[16][136];   // [k2][m], k2 = k/2 within BK=32
    __shared__ uint32_t Bs[16][136];   // [k2][n]

    int tid  = threadIdx.x;
    int warp = tid >> 5;
    int lane = tid & 31;
    int g    = lane >> 2;
    int t4   = lane & 3;
    int m0   = blockIdx.x * 128;
    int wm   = (warp >> 2) * 64;
    int wn   = (warp & 3) * 32;

    float acc[4][4][4];
#pragma unroll
    for (int mi = 0; mi < 4; mi++)
#pragma unroll
        for (int ni = 0; ni < 4; ni++)
#pragma unroll
            for (int r = 0; r < 4; r++) acc[mi][ni][r] = 0.0f;

    for (int k0 = 0; k0 < K; k0 += 32) {
        // A tile: 128 rows x 32 k = 1024 float4-quads, 4 per thread.
#pragma unroll
        for (int i = 0; i < 4; i++) {
            int l   = i * 256 + tid;
            int row = l >> 3;
            int q   = l & 7;
            int kc  = q * 4;
            int k2  = q * 2;
            int gr  = m0 + row;
            uint32_t w0 = 0, w1 = 0;
            if (gr < NN) {
                if (srcH) {
                    uint2 u = *(const uint2*)(g_Hh + (size_t)gr * 128 + k0 + kc);
                    w0 = u.x; w1 = u.y;          // already half2 (k,k+1),(k+2,k+3)
                } else {
                    float4 v = *(const float4*)(Aext + (size_t)gr * K + k0 + kc);
                    w0 = pack_h2(v.x, v.y);
                    w1 = pack_h2(v.z, v.w);
                }
            }
            As[k2 + 0][row] = w0;
            As[k2 + 1][row] = w1;
        }
        // B tile: pack W[k][n], W[k+1][n] into half2 words; 512 pair-tasks, 2/thread.
#pragma unroll
        for (int i = 0; i < 2; i++) {
            int l  = i * 256 + tid;
            int k2 = l >> 5;            // 0..15
            int nc = (l & 31) * 4;      // 0..124
            const float* Wk  = W + (size_t)(k0 + 2 * k2) * 128 + nc;
            float4 a = *(const float4*)Wk;
            float4 b = *(const float4*)(Wk + 128);
            uint4 o;
            o.x = pack_h2(a.x, b.x);
            o.y = pack_h2(a.y, b.y);
            o.z = pack_h2(a.z, b.z);
            o.w = pack_h2(a.w, b.w);
            *(uint4*)&Bs[k2][nc] = o;
        }
        __syncthreads();

#pragma unroll
        for (int kk2 = 0; kk2 < 16; kk2 += 8) {   // two k16 steps per BK=32
            uint32_t af[4][4];
#pragma unroll
            for (int mi = 0; mi < 4; mi++) {
                int m = wm + mi * 16 + g;
                af[mi][0] = As[kk2 + t4][m];
                af[mi][1] = As[kk2 + t4][m + 8];
                af[mi][2] = As[kk2 + t4 + 4][m];
                af[mi][3] = As[kk2 + t4 + 4][m + 8];
            }
            uint32_t bf[4][2];
#pragma unroll
            for (int ni = 0; ni < 4; ni++) {
                int n = wn + ni * 8 + g;
                bf[ni][0] = Bs[kk2 + t4][n];
                bf[ni][1] = Bs[kk2 + t4 + 4][n];
            }
#pragma unroll
            for (int mi = 0; mi < 4; mi++)
#pragma unroll
                for (int ni = 0; ni < 4; ni++)
                    mma_f16(acc[mi][ni], af[mi], bf[ni]);
        }
        __syncthreads();
    }

#pragma unroll
    for (int mi = 0; mi < 4; mi++) {
        int r0 = m0 + wm + mi * 16 + g;
        int r1 = r0 + 8;
        float d0 = 1.0f, d1 = 1.0f;
        if (scale_dis) {
            d0 = (r0 < NN) ? g_dis[r0] : 0.0f;
            d1 = (r1 < NN) ? g_dis[r1] : 0.0f;
        }
#pragma unroll
        for (int ni = 0; ni < 4; ni++) {
            int c = wn + ni * 8 + 2 * t4;
            if (r0 < NN) {
                __half2 h = __floats2half2_rn(acc[mi][ni][0] * d0, acc[mi][ni][1] * d0);
                *(__half2*)(g_Gh + (size_t)r0 * 128 + c) = h;
            }
            if (r1 < NN) {
                __half2 h = __floats2half2_rn(acc[mi][ni][2] * d1, acc[mi][ni][3] * d1);
                *(__half2*)(g_Gh + (size_t)r1 * 128 + c) = h;
            }
        }
    }
}

// ---------------- GEMM: [NN x 128(fp16)] @ [128 x 16] * dis[row] -> g_G16 (fp32) ------
__global__ __launch_bounds__(256) void gemm16_kernel(const float* __restrict__ W3)
{
    __shared__ float As[16][520];
    __shared__ float Bs[16][16];

    int tid = threadIdx.x;
    int m0  = blockIdx.x * 512;
    int tx  = tid & 1;
    int ty  = tid >> 1;

    float acc[4][8];
#pragma unroll
    for (int r = 0; r < 4; r++)
#pragma unroll
        for (int c = 0; c < 8; c++) acc[r][c] = 0.0f;

    for (int k0 = 0; k0 < 128; k0 += 16) {
#pragma unroll
        for (int i = 0; i < 8; i++) {
            int l   = i * 256 + tid;
            int row = l >> 2;
            int kc  = (l & 3) << 2;
            int gr  = m0 + row;
            float4 v = make_float4(0.f, 0.f, 0.f, 0.f);
            if (gr < NN) {
                uint2 u = *(const uint2*)(g_Hh + (size_t)gr * 128 + k0 + kc);
                float2 a0 = __half22float2(*(__half2*)&u.x);
                float2 a1 = __half22float2(*(__half2*)&u.y);
                v = make_float4(a0.x, a0.y, a1.x, a1.y);
            }
            As[kc + 0][row] = v.x;
            As[kc + 1][row] = v.y;
            As[kc + 2][row] = v.z;
            As[kc + 3][row] = v.w;
        }
        if (tid < 64) {
            int kr = tid >> 2;
            int nc = (tid & 3) << 2;
            *(float4*)&Bs[kr][nc] = *(const float4*)(W3 + (size_t)(k0 + kr) * 16 + nc);
        }
        __syncthreads();

#pragma unroll
        for (int k = 0; k < 16; k++) {
            float4 av = *(const float4*)&As[k][ty * 4];
            float a[4] = {av.x, av.y, av.z, av.w};
            float4 b0 = *(const float4*)&Bs[k][tx * 8];
            float4 b1 = *(const float4*)&Bs[k][tx * 8 + 4];
            float bb[8] = {b0.x,b0.y,b0.z,b0.w,b1.x,b1.y,b1.z,b1.w};
#pragma unroll
            for (int r = 0; r < 4; r++)
#pragma unroll
                for (int c = 0; c < 8; c++)
                    acc[r][c] += a[r] * bb[c];
        }
        __syncthreads();
    }

#pragma unroll
    for (int r = 0; r < 4; r++) {
        int gr = m0 + ty * 4 + r;
        if (gr < NN) {
            float d = g_dis[gr];
            float4 v0 = make_float4(acc[r][0]*d, acc[r][1]*d, acc[r][2]*d, acc[r][3]*d);
            float4 v1 = make_float4(acc[r][4]*d, acc[r][5]*d, acc[r][6]*d, acc[r][7]*d);
            *(float4*)(g_G16 + (size_t)gr * 16 + tx * 8)     = v0;
            *(float4*)(g_G16 + (size_t)gr * 16 + tx * 8 + 4) = v1;
        }
    }
}

// ---------------- Aggregation (128-wide, fp16 gather, fp16 H output) ----------------
// scale_src=1 (layer 1): H = relu(dis_i*(sum dis_s*G[s] + dis_i*G[i]) + b)
// scale_src=0 (layer 2): H = relu(dis_i*(sum G[s] + G[i]) + b)
__global__ __launch_bounds__(256) void agg128_kernel(const float* __restrict__ bias,
                                                     int scale_src)
{
    int gt   = blockIdx.x * blockDim.x + threadIdx.x;
    int node = gt >> 5;
    int lane = gt & 31;
    if (node >= NN) return;

    const uint2* __restrict__ Gv = (const uint2*)g_Gh;
    float d = g_dis[node];

    float4 acc = make_float4(0.f, 0.f, 0.f, 0.f);
    acc = h8_to_f4_sum(Gv[node * 32 + lane], scale_src ? d : 1.0f, acc);

    int j  = g_rowstart[node];
    int s1 = g_rowstart[node + 1];
    for (; j + 4 <= s1; j += 4) {
        int sa = g_csr[j],     sb = g_csr[j + 1];
        int sc = g_csr[j + 2], sd = g_csr[j + 3];
        uint2 va = Gv[sa * 32 + lane];
        uint2 vb = Gv[sb * 32 + lane];
        uint2 vc = Gv[sc * 32 + lane];
        uint2 vd = Gv[sd * 32 + lane];
        float wa = 1.0f, wb = 1.0f, wc = 1.0f, wd = 1.0f;
        if (scale_src) { wa = g_dis[sa]; wb = g_dis[sb]; wc = g_dis[sc]; wd = g_dis[sd]; }
        acc = h8_to_f4_sum(va, wa, acc);
        acc = h8_to_f4_sum(vb, wb, acc);
        acc = h8_to_f4_sum(vc, wc, acc);
        acc = h8_to_f4_sum(vd, wd, acc);
    }
    for (; j < s1; j++) {
        int s = g_csr[j];
        acc = h8_to_f4_sum(Gv[s * 32 + lane], scale_src ? g_dis[s] : 1.0f, acc);
    }

    float4 b = ((const float4*)bias)[lane];
    uint2 o;
    *(__half2*)&o.x = __floats2half2_rn(fmaxf(acc.x * d + b.x, 0.0f),
                                        fmaxf(acc.y * d + b.y, 0.0f));
    *(__half2*)&o.y = __floats2half2_rn(fmaxf(acc.z * d + b.z, 0.0f),
                                        fmaxf(acc.w * d + b.w, 0.0f));
    ((uint2*)g_Hh)[(size_t)node * 32 + lane] = o;
}

// ---------------- Aggregation (16-wide, final, fp32) ----------------
__global__ __launch_bounds__(256) void agg16_kernel(const float* __restrict__ bias,
                                                    float* __restrict__ out)
{
    int gt   = blockIdx.x * blockDim.x + threadIdx.x;
    int node = gt >> 2;
    int q    = gt & 3;
    if (node >= NN) return;

    const float4* __restrict__ Gv = (const float4*)g_G16;
    float4 acc = Gv[node * 4 + q];

    int j  = g_rowstart[node];
    int s1 = g_rowstart[node + 1];
    for (; j + 2 <= s1; j += 2) {
        int sa = g_csr[j], sb = g_csr[j + 1];
        float4 va = Gv[sa * 4 + q];
        float4 vb = Gv[sb * 4 + q];
        acc = f4add(acc, f4add(va, vb));
    }
    for (; j < s1; j++) acc = f4add(acc, Gv[g_csr[j] * 4 + q]);

    float d = g_dis[node];
    float4 b = ((const float4*)bias)[q];
    float4 r;
    r.x = acc.x * d + b.x;
    r.y = acc.y * d + b.y;
    r.z = acc.z * d + b.z;
    r.w = acc.w * d + b.w;
    ((float4*)out)[(size_t)node * 4 + q] = r;
}

// ---------------- launch ----------------
extern "C" void kernel_launch(void* const* d_in, const int* in_sizes, int n_in,
                              void* d_out, int out_size)
{
    const float* x  = (const float*)d_in[0];
    const void*  ei = d_in[1];                 // int32 or int64, detected per block
    const float* W1 = (const float*)d_in[2];
    const float* b1 = (const float*)d_in[3];
    const float* W2 = (const float*)d_in[4];
    const float* b2 = (const float*)d_in[5];
    const float* W3 = (const float*)d_in[6];
    const float* b3 = (const float*)d_in[7];
    float* out = (float*)d_out;

    // one-time host-side setup (first call = correctness run, outside capture)
    static cudaStream_t s2 = nullptr;
    static cudaEvent_t  evFork = nullptr, evGemm = nullptr;
    static void* p_deg = nullptr;
    if (!s2) {
        cudaStreamCreateWithFlags(&s2, cudaStreamNonBlocking);
        cudaEventCreateWithFlags(&evFork, cudaEventDisableTiming);
        cudaEventCreateWithFlags(&evGemm, cudaEventDisableTiming);
        cudaGetSymbolAddress(&p_deg, g_deg);
    }

    const int gemm_blocks   = (NN + 127) / 128;        // 391
    const int agg128_blocks = (NN * 32 + 255) / 256;   // 6250
    const int agg16_blocks  = (NN * 4 + 255) / 256;    // 782
    const int gemm16_blocks = (NN + 511) / 512;        // 98
    const int edge4_blocks  = (NE / 4 + 255) / 256;    // 625

    // Fork: GEMM-L1 (independent of preprocessing; dis deferred to agg)
    cudaEventRecord(evFork, 0);
    cudaStreamWaitEvent(s2, evFork, 0);
    gemm128_tc_kernel<<<gemm_blocks, 256, 0, s2>>>(x, W1, 256, 0, /*scale_dis=*/0);
    cudaEventRecord(evGemm, s2);

    // Main branch: preprocessing (memset node -> deg -> scan -> fill)
    cudaMemsetAsync(p_deg, 0, NN * sizeof(int), 0);
    deg_kernel<<<edge4_blocks, 256>>>(ei);
    scan_fused_kernel<<<SCAN_BLOCKS, 256>>>();
    fill_kernel<<<edge4_blocks, 256>>>(ei);

    // Join, then layer 1 aggregation (applies dis on both sides)
    cudaStreamWaitEvent(0, evGemm, 0);
    agg128_kernel<<<agg128_blocks, 256>>>(b1, /*scale_src=*/1);

    // Layer 2 (A = H fp16; dis in GEMM epilogue)
    gemm128_tc_kernel<<<gemm_blocks, 256>>>(nullptr, W2, 128, 1, /*scale_dis=*/1);
    agg128_kernel<<<agg128_blocks, 256>>>(b2, /*scale_src=*/0);

    // Layer 3: 128 -> 16, no relu (A = H fp16, fp32 math)
    gemm16_kernel<<<gemm16_blocks, 256>>>(W3);
    agg16_kernel<<<agg16_blocks, 256>>>(b3, out);
}